// round 14
// baseline (speedup 1.0000x reference)
#include <cuda_runtime.h>
#include <cuda_fp16.h>
#include <cstdint>

// ---------------- problem dims ----------------
#define BB 4
#define SS 1024
#define DDIM 1024
#define HH 16
#define HDIM 64
#define DFF 4096
#define MTOT (BB*SS)   // 4096

// ---------------- device scratch (no allocs allowed) ----------------
__device__ __half g_h    [MTOT*DDIM];                 // LN output (half)
__device__ __half g_qkvh [(size_t)MTOT*3*DDIM];       // fused q|k|v (half)
__device__ __half g_ctx  [MTOT*DDIM];                 // attention output (half)
__device__ float  g_x2   [MTOT*DDIM];
__device__ __half g_mid  [(size_t)MTOT*DFF];          // FFN mid (half)
// half weights
__device__ __half g_hwqkv[(size_t)DDIM*3*DDIM];       // [K=1024][N=3072] concat
__device__ __half g_hwo  [DDIM*DDIM];
__device__ __half g_hw1  [(size_t)DDIM*DFF];
__device__ __half g_hw2  [(size_t)DFF*DDIM];

// ---------------- helpers ----------------
__device__ __forceinline__ void cp16(uint32_t dst, const void* src) {
    asm volatile("cp.async.cg.shared.global [%0], [%1], 16;" :: "r"(dst), "l"(src));
}
__device__ __forceinline__ void cpcommit() { asm volatile("cp.async.commit_group;"); }
template<int N> __device__ __forceinline__ void cpwait() {
    asm volatile("cp.async.wait_group %0;" :: "n"(N));
}
__device__ __forceinline__ float gelu_tanh(float v) {
    const float c = 0.79788456080286535588f;  // sqrt(2/pi)
    float u = c * (v + 0.044715f * v * v * v);
    return 0.5f * v * (1.f + tanhf(u));
}

#define MMA_F16(acc, a0,a1,a2,a3, b0,b1) \
    asm volatile( \
        "mma.sync.aligned.m16n8k16.row.col.f32.f16.f16.f32 " \
        "{%0,%1,%2,%3},{%4,%5,%6,%7},{%8,%9},{%0,%1,%2,%3};\n" \
        : "+f"((acc)[0]), "+f"((acc)[1]), "+f"((acc)[2]), "+f"((acc)[3]) \
        : "r"(a0), "r"(a1), "r"(a2), "r"(a3), "r"(b0), "r"(b1))

#define LDSM_X4(r0,r1,r2,r3, addr) \
    asm volatile("ldmatrix.sync.aligned.m8n8.x4.shared.b16 {%0,%1,%2,%3}, [%4];" \
        : "=r"(r0), "=r"(r1), "=r"(r2), "=r"(r3) : "r"(addr))
#define LDSM_X4T(r0,r1,r2,r3, addr) \
    asm volatile("ldmatrix.sync.aligned.m8n8.x4.trans.shared.b16 {%0,%1,%2,%3}, [%4];" \
        : "=r"(r0), "=r"(r1), "=r"(r2), "=r"(r3) : "r"(addr))

// ---------------- merged weight prep: fp32 -> fp16 (one launch) ----------------
#define QKV_CH  (DDIM * 3 * DDIM / 4)                 // 786432
#define WO_CH   (DDIM * DDIM / 4)                     // 262144
#define W1_CH   (DDIM * DFF / 4)                      // 1048576
#define W2_CH   (DFF * DDIM / 4)                      // 1048576
#define TOT_CH  (QKV_CH + WO_CH + W1_CH + W2_CH)      // 3145728

__global__ void prep_weights(const float4* __restrict__ wq, const float4* __restrict__ wk,
                             const float4* __restrict__ wv, const float4* __restrict__ wo,
                             const float4* __restrict__ w1, const float4* __restrict__ w2,
                             uint2* __restrict__ hwqkv, uint2* __restrict__ hwo,
                             uint2* __restrict__ hw1,   uint2* __restrict__ hw2) {
    int i = blockIdx.x * 256 + threadIdx.x;
    float4 v; uint2* dst; int di;
    if (i < QKV_CH) {
        int k = i / 768, nc = i % 768;
        const float4* src = (nc < 256) ? wq : (nc < 512) ? wk : wv;
        v = src[k * 256 + (nc & 255)];
        dst = hwqkv; di = i;
    } else if (i < QKV_CH + WO_CH) {
        di = i - QKV_CH; v = wo[di]; dst = hwo;
    } else if (i < QKV_CH + WO_CH + W1_CH) {
        di = i - QKV_CH - WO_CH; v = w1[di]; dst = hw1;
    } else {
        di = i - QKV_CH - WO_CH - W1_CH; v = w2[di]; dst = hw2;
    }
    __half2 h01 = __floats2half2_rn(v.x, v.y);
    __half2 h23 = __floats2half2_rn(v.z, v.w);
    uint2 o; o.x = *(uint32_t*)&h01; o.y = *(uint32_t*)&h23;
    dst[di] = o;
}

// ---------------- LayerNorm (row = 1024), output fp16 ----------------
__global__ void ln_kernel(const float* __restrict__ x,
                          const float* __restrict__ scale,
                          const float* __restrict__ shift,
                          __half* __restrict__ out) {
    int row = blockIdx.x;
    int t = threadIdx.x;                 // 256 threads, 4 floats each
    const float4* xr = (const float4*)(x + (size_t)row * DDIM);
    float4 v = xr[t];
    float s  = v.x + v.y + v.z + v.w;
    float s2 = v.x*v.x + v.y*v.y + v.z*v.z + v.w*v.w;
    #pragma unroll
    for (int o = 16; o >= 1; o >>= 1) {
        s  += __shfl_xor_sync(0xffffffffu, s,  o);
        s2 += __shfl_xor_sync(0xffffffffu, s2, o);
    }
    __shared__ float red[2][8];
    __shared__ float bcast[2];
    int wid = t >> 5, lane = t & 31;
    if (lane == 0) { red[0][wid] = s; red[1][wid] = s2; }
    __syncthreads();
    if (t == 0) {
        float S = 0.f, S2 = 0.f;
        #pragma unroll
        for (int i = 0; i < 8; i++) { S += red[0][i]; S2 += red[1][i]; }
        float m = S * (1.f / DDIM);
        float var = S2 * (1.f / DDIM) - m * m;
        bcast[0] = m;
        bcast[1] = rsqrtf(var + 1e-5f);
    }
    __syncthreads();
    float m = bcast[0], inv = bcast[1];
    float4 sc = ((const float4*)scale)[t];
    float4 sh = ((const float4*)shift)[t];
    __half2 h01 = __floats2half2_rn(sc.x * (v.x - m) * inv + sh.x,
                                    sc.y * (v.y - m) * inv + sh.y);
    __half2 h23 = __floats2half2_rn(sc.z * (v.z - m) * inv + sh.z,
                                    sc.w * (v.w - m) * inv + sh.w);
    uint2 o2; o2.x = *(uint32_t*)&h01; o2.y = *(uint32_t*)&h23;
    ((uint2*)(out + (size_t)row * DDIM))[t] = o2;
}

// ---------------- FP16 mma GEMM, BKQ=64 ----------------
// EPI: 0 fp32 store, 1 +bias+res fp32 store, 2 half gelu store, 3 plain half store
#define BM 128
#define BN 128
#define BKQ 64
#define ASTH 72     // 144B rows: 9x16B units (odd) -> ldmatrix conflict-free
#define BSTH 136
#define NSTAGE 3

#define A_STG_H (BM * ASTH)    // 9216 halves
#define B_STG_H (BKQ * BSTH)   // 8704 halves
#define GEMM_SMEM ((NSTAGE * (A_STG_H + B_STG_H)) * 2)   // 107520 B

template<int EPI>
__global__ void __launch_bounds__(256, 2) gemm_kernel(
    const __half* __restrict__ A, const __half* __restrict__ Wt,
    const float* __restrict__ bias, const float* __restrict__ res,
    void* __restrict__ Cv, int Kdim, int Bld, int Cld)
{
    extern __shared__ __half smem[];
    __half* As = smem;
    __half* Bs = smem + NSTAGE * A_STG_H;

    const int tid  = threadIdx.x;
    const int bm0  = blockIdx.y * BM;
    const int bn0  = blockIdx.x * BN;
    const int wid  = tid >> 5, lane = tid & 31;
    const int wm   = wid >> 2;
    const int wn   = wid & 3;
    const int t4   = lane & 3;

    float acc[4][4][4];
    #pragma unroll
    for (int i = 0; i < 4; i++)
        #pragma unroll
        for (int j = 0; j < 4; j++)
            #pragma unroll
            for (int c = 0; c < 4; c++) acc[i][j][c] = 0.f;

    // ---- staging: 16B chunks (8 halves) ----
    // A: 128 rows x 8 chunks = 1024; thread -> rows tid>>3 + {0,32,64,96}, col tid&7
    // B: 64 rows x 16 chunks = 1024; thread -> rows tid>>4 + {0,16,32,48}, col tid&15
    const int arow = tid >> 3, ac8 = tid & 7;
    const int brow = tid >> 4, bc16 = tid & 15;
    const __half* AgBase = A  + (size_t)(bm0 + arow) * Kdim + ac8 * 8;
    const __half* BgBase = Wt + (size_t)brow * Bld + bn0 + bc16 * 8;
    const uint32_t AsW = (uint32_t)__cvta_generic_to_shared(&As[arow * ASTH + ac8 * 8]);
    const uint32_t BsW = (uint32_t)__cvta_generic_to_shared(&Bs[brow * BSTH + bc16 * 8]);

    // ---- ldmatrix lane addresses ----
    const int lrow = lane & 15;
    const int lcol = (lane >> 4) * 8;
    uint32_t aLd[4];
    #pragma unroll
    for (int i = 0; i < 4; i++)
        aLd[i] = (uint32_t)__cvta_generic_to_shared(
            &As[(wm * 64 + i * 16 + lrow) * ASTH + lcol]);
    const int bkc = (lane >> 3) & 1, bjg = lane >> 4, br8 = lane & 7;
    const uint32_t bLd = (uint32_t)__cvta_generic_to_shared(
        &Bs[(bkc * 8 + br8) * BSTH + wn * 32 + bjg * 8]);

    const int KT = Kdim / BKQ;

    auto issue = [&](int kt) {
        const int st = kt % NSTAGE;
        const __half* Ag = AgBase + kt * BKQ;
        const __half* Bg = BgBase + (size_t)kt * BKQ * Bld;
        uint32_t ad = AsW + st * (A_STG_H * 2);
        uint32_t bd = BsW + st * (B_STG_H * 2);
        #pragma unroll
        for (int r = 0; r < 4; r++) {
            cp16(ad + r * 32 * ASTH * 2, Ag + (size_t)(r * 32) * Kdim);
            cp16(bd + r * 16 * BSTH * 2, Bg + (size_t)(r * 16) * Bld);
        }
    };

    issue(0); cpcommit();
    issue(1); cpcommit();

    for (int kt = 0; kt < KT; kt++) {
        cpwait<1>();
        __syncthreads();

        if (kt + 2 < KT) issue(kt + 2);
        cpcommit();

        const int cb = kt % NSTAGE;
        const uint32_t aOff = cb * (A_STG_H * 2);
        const uint32_t bOff = cb * (B_STG_H * 2);

        #pragma unroll
        for (int s = 0; s < 4; s++) {          // four k16 steps per BKQ=64
            uint32_t afr[4][4], bfr[4][2];
            #pragma unroll
            for (int i = 0; i < 4; i++)
                LDSM_X4(afr[i][0], afr[i][1], afr[i][2], afr[i][3],
                        aLd[i] + aOff + s * 32);
            #pragma unroll
            for (int p = 0; p < 2; p++) {
                uint32_t r0, r1, r2, r3;
                LDSM_X4T(r0, r1, r2, r3, bLd + bOff + s * 16 * BSTH * 2 + p * 32);
                bfr[p*2  ][0] = r0; bfr[p*2  ][1] = r1;
                bfr[p*2+1][0] = r2; bfr[p*2+1][1] = r3;
            }
            #pragma unroll
            for (int i = 0; i < 4; i++)
                #pragma unroll
                for (int j = 0; j < 4; j++)
                    MMA_F16(acc[i][j], afr[i][0], afr[i][1], afr[i][2], afr[i][3],
                            bfr[j][0], bfr[j][1]);
        }
    }

    #pragma unroll
    for (int i = 0; i < 4; i++) {
        #pragma unroll
        for (int j = 0; j < 4; j++) {
            int r0 = bm0 + wm * 64 + i * 16 + (lane >> 2);
            int c0 = bn0 + wn * 32 + j * 8 + t4 * 2;
            #pragma unroll
            for (int half_ = 0; half_ < 2; half_++) {
                int r = r0 + half_ * 8;
                float vx = acc[i][j][half_ * 2], vy = acc[i][j][half_ * 2 + 1];
                if (EPI == 0) {
                    *(float2*)((float*)Cv + (size_t)r * Cld + c0) = make_float2(vx, vy);
                } else if (EPI == 1) {
                    float2 rr = *(const float2*)(res + (size_t)r * Cld + c0);
                    *(float2*)((float*)Cv + (size_t)r * Cld + c0) =
                        make_float2(vx + bias[c0] + rr.x, vy + bias[c0 + 1] + rr.y);
                } else if (EPI == 2) {
                    __half2 hv = __floats2half2_rn(gelu_tanh(vx + bias[c0]),
                                                   gelu_tanh(vy + bias[c0 + 1]));
                    *(__half2*)((__half*)Cv + (size_t)r * Cld + c0) = hv;
                } else {
                    *(__half2*)((__half*)Cv + (size_t)r * Cld + c0) =
                        __floats2half2_rn(vx, vy);
                }
            }
        }
    }
}

// ---------------- fp16 mma fused causal flash attention (proven R12) ----------------
#define QSTH 72
#define KSTH 72
#define VSTH 72
#define PSTH 72
#define ATTN_SMEM ((64*QSTH + 64*KSTH + 64*VSTH + 4*16*PSTH) * 2 + 64 * 4)  // 37120 B

__global__ void __launch_bounds__(128) attn_kernel(
    const __half* __restrict__ qkv, const int* __restrict__ mask,
    __half* __restrict__ ctx)
{
    extern __shared__ __half hsm[];
    __half* Qs = hsm;
    __half* Ks = Qs + 64 * QSTH;
    __half* Vs = Ks + 64 * KSTH;
    __half* Pb = Vs + 64 * VSTH;
    float*  Ms = (float*)(Pb + 4 * 16 * PSTH);

    const int b = blockIdx.z, h = blockIdx.y, qt = blockIdx.x;
    const int q0 = qt * 64;
    const int t = threadIdx.x;
    const int w = t >> 5, lane = t & 31;
    const int g = lane >> 2, t4 = lane & 3;
    __half* Pw = Pb + w * 16 * PSTH;

    {
        int row = t >> 1, ch = t & 1;
        const uint4* src = (const uint4*)(qkv + (size_t)(b * SS + q0 + row) * 3 * DDIM
                                          + h * HDIM) + ch * 4;
        __half2 scl = __floats2half2_rn(0.125f, 0.125f);
        uint4* dst = (uint4*)(Qs + row * QSTH + ch * 32);
        #pragma unroll
        for (int i = 0; i < 4; i++) {
            uint4 v = src[i];
            __half2* hp = (__half2*)&v;
            hp[0] = __hmul2(hp[0], scl); hp[1] = __hmul2(hp[1], scl);
            hp[2] = __hmul2(hp[2], scl); hp[3] = __hmul2(hp[3], scl);
            dst[i] = v;
        }
    }

    const int lrow = lane & 15;
    const uint32_t qLd = (uint32_t)__cvta_generic_to_shared(
        &Qs[(w * 16 + lrow) * QSTH + (lane >> 4) * 8]);
    const uint32_t pLd = (uint32_t)__cvta_generic_to_shared(
        &Pw[lrow * PSTH + (lane >> 4) * 8]);
    const uint32_t kLd = (uint32_t)__cvta_generic_to_shared(
        &Ks[((lane & 7) + ((lane >> 4) & 1) * 8) * KSTH + ((lane >> 3) & 1) * 8]);
    const int bkc = (lane >> 3) & 1, bjg = lane >> 4, br8 = lane & 7;
    const uint32_t vLd = (uint32_t)__cvta_generic_to_shared(
        &Vs[(bkc * 8 + br8) * VSTH + bjg * 8]);

    float O[8][4];
    #pragma unroll
    for (int j = 0; j < 8; j++)
        #pragma unroll
        for (int c = 0; c < 4; c++) O[j][c] = 0.f;
    float m0 = -1e30f, m1 = -1e30f, l0 = 0.f, l1 = 0.f;
    const int qg0 = q0 + w * 16 + g, qg1 = qg0 + 8;

    for (int kt = 0; kt <= qt; kt++) {
        __syncthreads();
        {
            int row = t >> 1, ch = t & 1;
            const __half* base = qkv + (size_t)(b * SS + kt * 64 + row) * 3 * DDIM
                                 + h * HDIM;
            const uint4* ks = (const uint4*)(base + DDIM) + ch * 4;
            const uint4* vs = (const uint4*)(base + 2 * DDIM) + ch * 4;
            uint4* kd = (uint4*)(Ks + row * KSTH + ch * 32);
            uint4* vd = (uint4*)(Vs + row * VSTH + ch * 32);
            #pragma unroll
            for (int i = 0; i < 4; i++) { kd[i] = ks[i]; vd[i] = vs[i]; }
            if (t < 64)
                Ms[t] = mask[b * SS + kt * 64 + t] ? 0.f : -1e30f;
        }
        __syncthreads();

        float s[8][4];
        #pragma unroll
        for (int j = 0; j < 8; j++)
            #pragma unroll
            for (int c = 0; c < 4; c++) s[j][c] = 0.f;

        #pragma unroll
        for (int s4 = 0; s4 < 4; s4++) {
            uint32_t a0, a1, a2, a3;
            LDSM_X4(a0, a1, a2, a3, qLd + s4 * 32);
            #pragma unroll
            for (int j2 = 0; j2 < 4; j2++) {
                uint32_t r0, r1, r2, r3;
                LDSM_X4(r0, r1, r2, r3, kLd + (j2 * 16 * KSTH + s4 * 16) * 2);
                MMA_F16(s[j2*2],   a0, a1, a2, a3, r0, r1);
                MMA_F16(s[j2*2+1], a0, a1, a2, a3, r2, r3);
            }
        }

        const bool diag = (kt == qt);
        float mt0 = -1e30f, mt1 = -1e30f;
        #pragma unroll
        for (int j = 0; j < 8; j++) {
            int n0 = j * 8 + 2 * t4;
            float pm0 = Ms[n0], pm1 = Ms[n0 + 1];
            float v0 = s[j][0] + pm0, v1 = s[j][1] + pm1;
            float v2 = s[j][2] + pm0, v3 = s[j][3] + pm1;
            if (diag) {
                int kg = kt * 64 + n0;
                if (kg     > qg0) v0 = -1e30f;
                if (kg + 1 > qg0) v1 = -1e30f;
                if (kg     > qg1) v2 = -1e30f;
                if (kg + 1 > qg1) v3 = -1e30f;
            }
            s[j][0] = v0; s[j][1] = v1; s[j][2] = v2; s[j][3] = v3;
            mt0 = fmaxf(mt0, fmaxf(v0, v1));
            mt1 = fmaxf(mt1, fmaxf(v2, v3));
        }
        mt0 = fmaxf(mt0, __shfl_xor_sync(0xffffffffu, mt0, 1));
        mt0 = fmaxf(mt0, __shfl_xor_sync(0xffffffffu, mt0, 2));
        mt1 = fmaxf(mt1, __shfl_xor_sync(0xffffffffu, mt1, 1));
        mt1 = fmaxf(mt1, __shfl_xor_sync(0xffffffffu, mt1, 2));

        float mn0 = fmaxf(m0, mt0), mn1 = fmaxf(m1, mt1);
        float corr0 = __expf(m0 - mn0), corr1 = __expf(m1 - mn1);
        m0 = mn0; m1 = mn1;

        float ls0 = 0.f, ls1 = 0.f;
        #pragma unroll
        for (int j = 0; j < 8; j++) {
            float p0 = __expf(s[j][0] - mn0);
            float p1 = __expf(s[j][1] - mn0);
            float p2 = __expf(s[j][2] - mn1);
            float p3 = __expf(s[j][3] - mn1);
            ls0 += p0 + p1; ls1 += p2 + p3;
            int n0 = j * 8 + 2 * t4;
            *(__half2*)&Pw[g * PSTH + n0]       = __floats2half2_rn(p0, p1);
            *(__half2*)&Pw[(g + 8) * PSTH + n0] = __floats2half2_rn(p2, p3);
        }
        ls0 += __shfl_xor_sync(0xffffffffu, ls0, 1);
        ls0 += __shfl_xor_sync(0xffffffffu, ls0, 2);
        ls1 += __shfl_xor_sync(0xffffffffu, ls1, 1);
        ls1 += __shfl_xor_sync(0xffffffffu, ls1, 2);
        l0 = l0 * corr0 + ls0;
        l1 = l1 * corr1 + ls1;

        #pragma unroll
        for (int j = 0; j < 8; j++) {
            O[j][0] *= corr0; O[j][1] *= corr0;
            O[j][2] *= corr1; O[j][3] *= corr1;
        }
        __syncwarp();

        #pragma unroll
        for (int s4 = 0; s4 < 4; s4++) {
            uint32_t a0, a1, a2, a3;
            LDSM_X4(a0, a1, a2, a3, pLd + s4 * 32);
            #pragma unroll
            for (int p = 0; p < 4; p++) {
                uint32_t r0, r1, r2, r3;
                LDSM_X4T(r0, r1, r2, r3, vLd + (s4 * 16 * VSTH + p * 16) * 2);
                MMA_F16(O[p*2],   a0, a1, a2, a3, r0, r1);
                MMA_F16(O[p*2+1], a0, a1, a2, a3, r2, r3);
            }
        }
        __syncwarp();
    }

    float inv0 = 1.f / l0, inv1 = 1.f / l1;
    __half* o0 = ctx + (size_t)(b * SS + qg0) * DDIM + h * HDIM;
    __half* o1 = ctx + (size_t)(b * SS + qg1) * DDIM + h * HDIM;
    #pragma unroll
    for (int j = 0; j < 8; j++) {
        int n0 = j * 8 + 2 * t4;
        *(__half2*)(o0 + n0) = __floats2half2_rn(O[j][0] * inv0, O[j][1] * inv0);
        *(__half2*)(o1 + n0) = __floats2half2_rn(O[j][2] * inv1, O[j][3] * inv1);
    }
}

// ---------------- launch ----------------
extern "C" void kernel_launch(void* const* d_in, const int* in_sizes, int n_in,
                              void* d_out, int out_size) {
    const float* x     = (const float*)d_in[0];
    const int*   amask = (const int*)  d_in[1];
    const float* wq    = (const float*)d_in[2];
    const float* wk    = (const float*)d_in[3];
    const float* wv    = (const float*)d_in[4];
    const float* wo    = (const float*)d_in[5];
    const float* bo    = (const float*)d_in[6];
    const float* ln1s  = (const float*)d_in[7];
    const float* ln1b  = (const float*)d_in[8];
    const float* ln2s  = (const float*)d_in[9];
    const float* ln2b  = (const float*)d_in[10];
    const float* w1    = (const float*)d_in[11];
    const float* b1    = (const float*)d_in[12];
    const float* w2    = (const float*)d_in[13];
    const float* b2    = (const float*)d_in[14];
    float* out = (float*)d_out;

    __half *h, *qkvh, *ctx, *mid, *hwqkv, *hwo, *hw1, *hw2;
    float *x2;
    cudaGetSymbolAddress((void**)&h,     g_h);
    cudaGetSymbolAddress((void**)&qkvh,  g_qkvh);
    cudaGetSymbolAddress((void**)&ctx,   g_ctx);
    cudaGetSymbolAddress((void**)&x2,    g_x2);
    cudaGetSymbolAddress((void**)&mid,   g_mid);
    cudaGetSymbolAddress((void**)&hwqkv, g_hwqkv);
    cudaGetSymbolAddress((void**)&hwo,   g_hwo);
    cudaGetSymbolAddress((void**)&hw1,   g_hw1);
    cudaGetSymbolAddress((void**)&hw2,   g_hw2);

    cudaFuncSetAttribute(gemm_kernel<1>, cudaFuncAttributeMaxDynamicSharedMemorySize, GEMM_SMEM);
    cudaFuncSetAttribute(gemm_kernel<2>, cudaFuncAttributeMaxDynamicSharedMemorySize, GEMM_SMEM);
    cudaFuncSetAttribute(gemm_kernel<3>, cudaFuncAttributeMaxDynamicSharedMemorySize, GEMM_SMEM);
    cudaFuncSetAttribute(attn_kernel,    cudaFuncAttributeMaxDynamicSharedMemorySize, ATTN_SMEM);

    // merged weight prep (single launch)
    prep_weights<<<TOT_CH/256, 256>>>((const float4*)wq, (const float4*)wk,
                                      (const float4*)wv, (const float4*)wo,
                                      (const float4*)w1, (const float4*)w2,
                                      (uint2*)hwqkv, (uint2*)hwo,
                                      (uint2*)hw1,   (uint2*)hw2);

    // --- attention half ---
    ln_kernel<<<MTOT, 256>>>(x, ln1s, ln1b, h);
    gemm_kernel<3><<<dim3(3*DDIM/BN, MTOT/BM), 256, GEMM_SMEM>>>(
        h, hwqkv, nullptr, nullptr, qkvh, DDIM, 3*DDIM, 3*DDIM);
    attn_kernel<<<dim3(SS/64, HH, BB), 128, ATTN_SMEM>>>(qkvh, amask, ctx);
    gemm_kernel<1><<<dim3(DDIM/BN, MTOT/BM), 256, GEMM_SMEM>>>(
        ctx, hwo, bo, x, x2, DDIM, DDIM, DDIM);

    // --- FFN half ---
    ln_kernel<<<MTOT, 256>>>(x2, ln2s, ln2b, h);
    gemm_kernel<2><<<dim3(DFF/BN, MTOT/BM), 256, GEMM_SMEM>>>(
        h, hw1, b1, nullptr, mid, DDIM, DFF, DFF);
    gemm_kernel<1><<<dim3(DDIM/BN, MTOT/BM), 256, GEMM_SMEM>>>(
        mid, hw2, b2, x2, out, DFF, DDIM, DDIM);
}

// round 15
// speedup vs baseline: 1.0527x; 1.0527x over previous
#include <cuda_runtime.h>
#include <cuda_fp16.h>
#include <cstdint>

// ---------------- problem dims ----------------
#define BB 4
#define SS 1024
#define DDIM 1024
#define HH 16
#define HDIM 64
#define DFF 4096
#define MTOT (BB*SS)   // 4096

// ---------------- device scratch (no allocs allowed) ----------------
__device__ __half g_h    [MTOT*DDIM];                 // LN output (half)
__device__ __half g_qkvh [(size_t)MTOT*3*DDIM];       // fused q|k|v (half)
__device__ __half g_ctx  [MTOT*DDIM];                 // attention output (half)
__device__ float  g_x2   [MTOT*DDIM];
__device__ __half g_mid  [(size_t)MTOT*DFF];          // FFN mid (half)
// half weights
__device__ __half g_hwqkv[(size_t)DDIM*3*DDIM];       // [K=1024][N=3072] concat
__device__ __half g_hwo  [DDIM*DDIM];
__device__ __half g_hw1  [(size_t)DDIM*DFF];
__device__ __half g_hw2  [(size_t)DFF*DDIM];

// ---------------- helpers ----------------
__device__ __forceinline__ void cp16(uint32_t dst, const void* src) {
    asm volatile("cp.async.cg.shared.global [%0], [%1], 16;" :: "r"(dst), "l"(src));
}
__device__ __forceinline__ void cpcommit() { asm volatile("cp.async.commit_group;"); }
template<int N> __device__ __forceinline__ void cpwait() {
    asm volatile("cp.async.wait_group %0;" :: "n"(N));
}
__device__ __forceinline__ float gelu_tanh(float v) {
    const float c = 0.79788456080286535588f;  // sqrt(2/pi)
    float u = c * (v + 0.044715f * v * v * v);
    return 0.5f * v * (1.f + tanhf(u));
}

#define MMA_F16(acc, a0,a1,a2,a3, b0,b1) \
    asm volatile( \
        "mma.sync.aligned.m16n8k16.row.col.f32.f16.f16.f32 " \
        "{%0,%1,%2,%3},{%4,%5,%6,%7},{%8,%9},{%0,%1,%2,%3};\n" \
        : "+f"((acc)[0]), "+f"((acc)[1]), "+f"((acc)[2]), "+f"((acc)[3]) \
        : "r"(a0), "r"(a1), "r"(a2), "r"(a3), "r"(b0), "r"(b1))

#define LDSM_X4(r0,r1,r2,r3, addr) \
    asm volatile("ldmatrix.sync.aligned.m8n8.x4.shared.b16 {%0,%1,%2,%3}, [%4];" \
        : "=r"(r0), "=r"(r1), "=r"(r2), "=r"(r3) : "r"(addr))
#define LDSM_X4T(r0,r1,r2,r3, addr) \
    asm volatile("ldmatrix.sync.aligned.m8n8.x4.trans.shared.b16 {%0,%1,%2,%3}, [%4];" \
        : "=r"(r0), "=r"(r1), "=r"(r2), "=r"(r3) : "r"(addr))

// ---------------- merged weight prep: fp32 -> fp16 (one launch) ----------------
#define QKV_CH  (DDIM * 3 * DDIM / 4)                 // 786432
#define WO_CH   (DDIM * DDIM / 4)                     // 262144
#define W1_CH   (DDIM * DFF / 4)                      // 1048576
#define W2_CH   (DFF * DDIM / 4)                      // 1048576
#define TOT_CH  (QKV_CH + WO_CH + W1_CH + W2_CH)      // 3145728

__global__ void prep_weights(const float4* __restrict__ wq, const float4* __restrict__ wk,
                             const float4* __restrict__ wv, const float4* __restrict__ wo,
                             const float4* __restrict__ w1, const float4* __restrict__ w2,
                             uint2* __restrict__ hwqkv, uint2* __restrict__ hwo,
                             uint2* __restrict__ hw1,   uint2* __restrict__ hw2) {
    int i = blockIdx.x * 256 + threadIdx.x;
    float4 v; uint2* dst; int di;
    if (i < QKV_CH) {
        int k = i / 768, nc = i % 768;
        const float4* src = (nc < 256) ? wq : (nc < 512) ? wk : wv;
        v = src[k * 256 + (nc & 255)];
        dst = hwqkv; di = i;
    } else if (i < QKV_CH + WO_CH) {
        di = i - QKV_CH; v = wo[di]; dst = hwo;
    } else if (i < QKV_CH + WO_CH + W1_CH) {
        di = i - QKV_CH - WO_CH; v = w1[di]; dst = hw1;
    } else {
        di = i - QKV_CH - WO_CH - W1_CH; v = w2[di]; dst = hw2;
    }
    __half2 h01 = __floats2half2_rn(v.x, v.y);
    __half2 h23 = __floats2half2_rn(v.z, v.w);
    uint2 o; o.x = *(uint32_t*)&h01; o.y = *(uint32_t*)&h23;
    dst[di] = o;
}

// ---------------- LayerNorm (row = 1024), output fp16 ----------------
__global__ void ln_kernel(const float* __restrict__ x,
                          const float* __restrict__ scale,
                          const float* __restrict__ shift,
                          __half* __restrict__ out) {
    int row = blockIdx.x;
    int t = threadIdx.x;
    const float4* xr = (const float4*)(x + (size_t)row * DDIM);
    float4 v = xr[t];
    float s  = v.x + v.y + v.z + v.w;
    float s2 = v.x*v.x + v.y*v.y + v.z*v.z + v.w*v.w;
    #pragma unroll
    for (int o = 16; o >= 1; o >>= 1) {
        s  += __shfl_xor_sync(0xffffffffu, s,  o);
        s2 += __shfl_xor_sync(0xffffffffu, s2, o);
    }
    __shared__ float red[2][8];
    __shared__ float bcast[2];
    int wid = t >> 5, lane = t & 31;
    if (lane == 0) { red[0][wid] = s; red[1][wid] = s2; }
    __syncthreads();
    if (t == 0) {
        float S = 0.f, S2 = 0.f;
        #pragma unroll
        for (int i = 0; i < 8; i++) { S += red[0][i]; S2 += red[1][i]; }
        float m = S * (1.f / DDIM);
        float var = S2 * (1.f / DDIM) - m * m;
        bcast[0] = m;
        bcast[1] = rsqrtf(var + 1e-5f);
    }
    __syncthreads();
    float m = bcast[0], inv = bcast[1];
    float4 sc = ((const float4*)scale)[t];
    float4 sh = ((const float4*)shift)[t];
    __half2 h01 = __floats2half2_rn(sc.x * (v.x - m) * inv + sh.x,
                                    sc.y * (v.y - m) * inv + sh.y);
    __half2 h23 = __floats2half2_rn(sc.z * (v.z - m) * inv + sh.z,
                                    sc.w * (v.w - m) * inv + sh.w);
    uint2 o2; o2.x = *(uint32_t*)&h01; o2.y = *(uint32_t*)&h23;
    ((uint2*)(out + (size_t)row * DDIM))[t] = o2;
}

// ---------------- FP16 mma GEMM (proven R12: BKQ=32) ----------------
// EPI: 0 fp32 store, 1 +bias+res fp32 store, 2 half gelu store, 3 plain half store
#define BM 128
#define BN 128
#define BKQ 32
#define ASTH 40
#define BSTH 136
#define NSTAGE 3

#define A_STG_H (BM * ASTH)    // 5120 halves
#define B_STG_H (BKQ * BSTH)   // 4352 halves
#define GEMM_SMEM ((NSTAGE * (A_STG_H + B_STG_H)) * 2)   // 56832 B

template<int EPI>
__global__ void __launch_bounds__(256, 2) gemm_kernel(
    const __half* __restrict__ A, const __half* __restrict__ Wt,
    const float* __restrict__ bias, const float* __restrict__ res,
    void* __restrict__ Cv, int Kdim, int Bld, int Cld)
{
    extern __shared__ __half smem[];
    __half* As = smem;
    __half* Bs = smem + NSTAGE * A_STG_H;

    const int tid  = threadIdx.x;
    const int bm0  = blockIdx.y * BM;
    const int bn0  = blockIdx.x * BN;
    const int wid  = tid >> 5, lane = tid & 31;
    const int wm   = wid >> 2;
    const int wn   = wid & 3;
    const int t4   = lane & 3;

    float acc[4][4][4];
    #pragma unroll
    for (int i = 0; i < 4; i++)
        #pragma unroll
        for (int j = 0; j < 4; j++)
            #pragma unroll
            for (int c = 0; c < 4; c++) acc[i][j][c] = 0.f;

    const int arow = tid >> 2, ac8 = tid & 3;
    const int brow = tid >> 4, bc16 = tid & 15;
    const __half* AgBase = A  + (size_t)(bm0 + arow) * Kdim + ac8 * 8;
    const __half* BgBase = Wt + (size_t)brow * Bld + bn0 + bc16 * 8;
    const uint32_t AsW = (uint32_t)__cvta_generic_to_shared(&As[arow * ASTH + ac8 * 8]);
    const uint32_t BsW = (uint32_t)__cvta_generic_to_shared(&Bs[brow * BSTH + bc16 * 8]);

    const int lrow = lane & 15;
    const int lcol = (lane >> 4) * 8;
    uint32_t aLd[4];
    #pragma unroll
    for (int i = 0; i < 4; i++)
        aLd[i] = (uint32_t)__cvta_generic_to_shared(
            &As[(wm * 64 + i * 16 + lrow) * ASTH + lcol]);
    const int bkc = (lane >> 3) & 1, bjg = lane >> 4, br8 = lane & 7;
    const uint32_t bLd = (uint32_t)__cvta_generic_to_shared(
        &Bs[(bkc * 8 + br8) * BSTH + wn * 32 + bjg * 8]);

    const int KT = Kdim / BKQ;

    auto issue = [&](int kt) {
        const int st = kt % NSTAGE;
        const __half* Ag = AgBase + kt * BKQ;
        const __half* Bg = BgBase + (size_t)kt * BKQ * Bld;
        uint32_t ad = AsW + st * (A_STG_H * 2);
        uint32_t bd = BsW + st * (B_STG_H * 2);
        cp16(ad,                 Ag);
        cp16(ad + 64 * ASTH * 2, Ag + (size_t)64 * Kdim);
        cp16(bd,                 Bg);
        cp16(bd + 16 * BSTH * 2, Bg + (size_t)16 * Bld);
    };

    issue(0); cpcommit();
    issue(1); cpcommit();

    for (int kt = 0; kt < KT; kt++) {
        cpwait<1>();
        __syncthreads();

        if (kt + 2 < KT) issue(kt + 2);
        cpcommit();

        const int cb = kt % NSTAGE;
        const uint32_t aOff = cb * (A_STG_H * 2);
        const uint32_t bOff = cb * (B_STG_H * 2);

        #pragma unroll
        for (int s = 0; s < 2; s++) {
            uint32_t afr[4][4], bfr[4][2];
            #pragma unroll
            for (int i = 0; i < 4; i++)
                LDSM_X4(afr[i][0], afr[i][1], afr[i][2], afr[i][3],
                        aLd[i] + aOff + s * 32);
            #pragma unroll
            for (int p = 0; p < 2; p++) {
                uint32_t r0, r1, r2, r3;
                LDSM_X4T(r0, r1, r2, r3, bLd + bOff + s * 16 * BSTH * 2 + p * 32);
                bfr[p*2  ][0] = r0; bfr[p*2  ][1] = r1;
                bfr[p*2+1][0] = r2; bfr[p*2+1][1] = r3;
            }
            #pragma unroll
            for (int i = 0; i < 4; i++)
                #pragma unroll
                for (int j = 0; j < 4; j++)
                    MMA_F16(acc[i][j], afr[i][0], afr[i][1], afr[i][2], afr[i][3],
                            bfr[j][0], bfr[j][1]);
        }
    }

    #pragma unroll
    for (int i = 0; i < 4; i++) {
        #pragma unroll
        for (int j = 0; j < 4; j++) {
            int r0 = bm0 + wm * 64 + i * 16 + (lane >> 2);
            int c0 = bn0 + wn * 32 + j * 8 + t4 * 2;
            #pragma unroll
            for (int half_ = 0; half_ < 2; half_++) {
                int r = r0 + half_ * 8;
                float vx = acc[i][j][half_ * 2], vy = acc[i][j][half_ * 2 + 1];
                if (EPI == 0) {
                    *(float2*)((float*)Cv + (size_t)r * Cld + c0) = make_float2(vx, vy);
                } else if (EPI == 1) {
                    float2 rr = *(const float2*)(res + (size_t)r * Cld + c0);
                    *(float2*)((float*)Cv + (size_t)r * Cld + c0) =
                        make_float2(vx + bias[c0] + rr.x, vy + bias[c0 + 1] + rr.y);
                } else if (EPI == 2) {
                    __half2 hv = __floats2half2_rn(gelu_tanh(vx + bias[c0]),
                                                   gelu_tanh(vy + bias[c0 + 1]));
                    *(__half2*)((__half*)Cv + (size_t)r * Cld + c0) = hv;
                } else {
                    *(__half2*)((__half*)Cv + (size_t)r * Cld + c0) =
                        __floats2half2_rn(vx, vy);
                }
            }
        }
    }
}

// ---------------- fp16 mma fused causal flash attention, 128-q blocks ----------------
// 8 warps x 16 q-rows; cp.async double-buffered 64-row K/V tiles; single sync/tile.
#define QSTH 72
#define KSTH 72
#define VSTH 72
#define PSTH 72
#define QROWS 128
#define ATTN_SMEM ((QROWS*QSTH + 2*64*KSTH + 2*64*VSTH + 8*16*PSTH) * 2 + 2*64*4)  // 74240 B

__global__ void __launch_bounds__(256) attn_kernel(
    const __half* __restrict__ qkv, const int* __restrict__ mask,
    __half* __restrict__ ctx)
{
    extern __shared__ __half hsm[];
    __half* Qs = hsm;                             // QROWS*QSTH
    __half* Ks = Qs + QROWS * QSTH;               // 2 x 64*KSTH
    __half* Vs = Ks + 2 * 64 * KSTH;              // 2 x 64*VSTH
    __half* Pb = Vs + 2 * 64 * VSTH;              // 8 x 16*PSTH
    float*  Ms = (float*)(Pb + 8 * 16 * PSTH);    // 2 x 64

    const int b = blockIdx.z, h = blockIdx.y, qt = blockIdx.x;
    const int q0 = qt * QROWS;
    const int t = threadIdx.x;
    const int w = t >> 5, lane = t & 31;
    const int g = lane >> 2, t4 = lane & 3;
    __half* Pw = Pb + w * 16 * PSTH;

    // ---- stage Q (scaled by 1/8 — exact in fp16): 256 thr x 32 halves ----
    {
        int row = t >> 1, ch = t & 1;
        const uint4* src = (const uint4*)(qkv + (size_t)(b * SS + q0 + row) * 3 * DDIM
                                          + h * HDIM) + ch * 4;
        __half2 scl = __floats2half2_rn(0.125f, 0.125f);
        uint4* dst = (uint4*)(Qs + row * QSTH + ch * 32);
        #pragma unroll
        for (int i = 0; i < 4; i++) {
            uint4 v = src[i];
            __half2* hp = (__half2*)&v;
            hp[0] = __hmul2(hp[0], scl); hp[1] = __hmul2(hp[1], scl);
            hp[2] = __hmul2(hp[2], scl); hp[3] = __hmul2(hp[3], scl);
            dst[i] = v;
        }
    }

    // ---- K/V cp.async staging: thread -> row t>>2, cols (t&3)*16 + {0,8} ----
    const int krow = t >> 2;
    const int kcol = (t & 3) * 16;
    const uint32_t KsW = (uint32_t)__cvta_generic_to_shared(&Ks[krow * KSTH + kcol]);
    const uint32_t VsW = (uint32_t)__cvta_generic_to_shared(&Vs[krow * VSTH + kcol]);

    auto issueKV = [&](int kt) {
        int st = kt & 1;
        const __half* base = qkv + (size_t)(b * SS + kt * 64 + krow) * 3 * DDIM
                             + h * HDIM + kcol;
        uint32_t ko = KsW + st * (64 * KSTH * 2);
        uint32_t vo = VsW + st * (64 * VSTH * 2);
        cp16(ko,      base + DDIM);
        cp16(ko + 16, base + DDIM + 8);
        cp16(vo,      base + 2 * DDIM);
        cp16(vo + 16, base + 2 * DDIM + 8);
    };

    // ---- ldmatrix lane addresses (stage offset added at use) ----
    const int lrow = lane & 15;
    const uint32_t qLd = (uint32_t)__cvta_generic_to_shared(
        &Qs[(w * 16 + lrow) * QSTH + (lane >> 4) * 8]);
    const uint32_t pLd = (uint32_t)__cvta_generic_to_shared(
        &Pw[lrow * PSTH + (lane >> 4) * 8]);
    const uint32_t kLd = (uint32_t)__cvta_generic_to_shared(
        &Ks[((lane & 7) + ((lane >> 4) & 1) * 8) * KSTH + ((lane >> 3) & 1) * 8]);
    const int bkc = (lane >> 3) & 1, bjg = lane >> 4, br8 = lane & 7;
    const uint32_t vLd = (uint32_t)__cvta_generic_to_shared(
        &Vs[(bkc * 8 + br8) * VSTH + bjg * 8]);

    float O[8][4];
    #pragma unroll
    for (int j = 0; j < 8; j++)
        #pragma unroll
        for (int c = 0; c < 4; c++) O[j][c] = 0.f;
    float m0 = -1e30f, m1 = -1e30f, l0 = 0.f, l1 = 0.f;
    const int qg0 = q0 + w * 16 + g, qg1 = qg0 + 8;
    const int myqmax = q0 + w * 16 + 15;
    const int ktmax = (q0 + QROWS - 1) >> 6;   // 2*qt + 1

    // prologue
    issueKV(0); cpcommit();
    if (t < 64) Ms[t] = mask[b * SS + t] ? 0.f : -1e30f;

    for (int kt = 0; kt <= ktmax; kt++) {
        cpwait<0>();
        __syncthreads();          // tile kt staged & visible; prev compute done

        if (kt < ktmax) {
            issueKV(kt + 1);
            cpcommit();
            if (t < 64)
                Ms[((kt + 1) & 1) * 64 + t] =
                    mask[b * SS + (kt + 1) * 64 + t] ? 0.f : -1e30f;
        }

        if (kt * 64 <= myqmax) {    // warp-uniform causal skip
            const uint32_t kOff = (kt & 1) * (64 * KSTH * 2);
            const uint32_t vOff = (kt & 1) * (64 * VSTH * 2);
            const float* Msb = Ms + (kt & 1) * 64;

            // ---- S = Q @ K^T ----
            float s[8][4];
            #pragma unroll
            for (int j = 0; j < 8; j++)
                #pragma unroll
                for (int c = 0; c < 4; c++) s[j][c] = 0.f;

            #pragma unroll
            for (int s4 = 0; s4 < 4; s4++) {
                uint32_t a0, a1, a2, a3;
                LDSM_X4(a0, a1, a2, a3, qLd + s4 * 32);
                #pragma unroll
                for (int j2 = 0; j2 < 4; j2++) {
                    uint32_t r0, r1, r2, r3;
                    LDSM_X4(r0, r1, r2, r3,
                            kLd + kOff + (j2 * 16 * KSTH + s4 * 16) * 2);
                    MMA_F16(s[j2*2],   a0, a1, a2, a3, r0, r1);
                    MMA_F16(s[j2*2+1], a0, a1, a2, a3, r2, r3);
                }
            }

            // ---- mask + online softmax ----
            const bool diag = (kt * 64 + 63 > q0 + w * 16);
            float mt0 = -1e30f, mt1 = -1e30f;
            #pragma unroll
            for (int j = 0; j < 8; j++) {
                int n0 = j * 8 + 2 * t4;
                float pm0 = Msb[n0], pm1 = Msb[n0 + 1];
                float v0 = s[j][0] + pm0, v1 = s[j][1] + pm1;
                float v2 = s[j][2] + pm0, v3 = s[j][3] + pm1;
                if (diag) {
                    int kg = kt * 64 + n0;
                    if (kg     > qg0) v0 = -1e30f;
                    if (kg + 1 > qg0) v1 = -1e30f;
                    if (kg     > qg1) v2 = -1e30f;
                    if (kg + 1 > qg1) v3 = -1e30f;
                }
                s[j][0] = v0; s[j][1] = v1; s[j][2] = v2; s[j][3] = v3;
                mt0 = fmaxf(mt0, fmaxf(v0, v1));
                mt1 = fmaxf(mt1, fmaxf(v2, v3));
            }
            mt0 = fmaxf(mt0, __shfl_xor_sync(0xffffffffu, mt0, 1));
            mt0 = fmaxf(mt0, __shfl_xor_sync(0xffffffffu, mt0, 2));
            mt1 = fmaxf(mt1, __shfl_xor_sync(0xffffffffu, mt1, 1));
            mt1 = fmaxf(mt1, __shfl_xor_sync(0xffffffffu, mt1, 2));

            float mn0 = fmaxf(m0, mt0), mn1 = fmaxf(m1, mt1);
            float corr0 = __expf(m0 - mn0), corr1 = __expf(m1 - mn1);
            m0 = mn0; m1 = mn1;

            float ls0 = 0.f, ls1 = 0.f;
            #pragma unroll
            for (int j = 0; j < 8; j++) {
                float p0 = __expf(s[j][0] - mn0);
                float p1 = __expf(s[j][1] - mn0);
                float p2 = __expf(s[j][2] - mn1);
                float p3 = __expf(s[j][3] - mn1);
                ls0 += p0 + p1; ls1 += p2 + p3;
                int n0 = j * 8 + 2 * t4;
                *(__half2*)&Pw[g * PSTH + n0]       = __floats2half2_rn(p0, p1);
                *(__half2*)&Pw[(g + 8) * PSTH + n0] = __floats2half2_rn(p2, p3);
            }
            ls0 += __shfl_xor_sync(0xffffffffu, ls0, 1);
            ls0 += __shfl_xor_sync(0xffffffffu, ls0, 2);
            ls1 += __shfl_xor_sync(0xffffffffu, ls1, 1);
            ls1 += __shfl_xor_sync(0xffffffffu, ls1, 2);
            l0 = l0 * corr0 + ls0;
            l1 = l1 * corr1 + ls1;

            #pragma unroll
            for (int j = 0; j < 8; j++) {
                O[j][0] *= corr0; O[j][1] *= corr0;
                O[j][2] *= corr1; O[j][3] *= corr1;
            }
            __syncwarp();

            // ---- O += P @ V ----
            #pragma unroll
            for (int s4 = 0; s4 < 4; s4++) {
                uint32_t a0, a1, a2, a3;
                LDSM_X4(a0, a1, a2, a3, pLd + s4 * 32);
                #pragma unroll
                for (int p = 0; p < 4; p++) {
                    uint32_t r0, r1, r2, r3;
                    LDSM_X4T(r0, r1, r2, r3,
                             vLd + vOff + (s4 * 16 * VSTH + p * 16) * 2);
                    MMA_F16(O[p*2],   a0, a1, a2, a3, r0, r1);
                    MMA_F16(O[p*2+1], a0, a1, a2, a3, r2, r3);
                }
            }
            __syncwarp();
        }
    }

    // ---- final normalize + half store ----
    float inv0 = 1.f / l0, inv1 = 1.f / l1;
    __half* o0 = ctx + (size_t)(b * SS + qg0) * DDIM + h * HDIM;
    __half* o1 = ctx + (size_t)(b * SS + qg1) * DDIM + h * HDIM;
    #pragma unroll
    for (int j = 0; j < 8; j++) {
        int n0 = j * 8 + 2 * t4;
        *(__half2*)(o0 + n0) = __floats2half2_rn(O[j][0] * inv0, O[j][1] * inv0);
        *(__half2*)(o1 + n0) = __floats2half2_rn(O[j][2] * inv1, O[j][3] * inv1);
    }
}

// ---------------- launch ----------------
extern "C" void kernel_launch(void* const* d_in, const int* in_sizes, int n_in,
                              void* d_out, int out_size) {
    const float* x     = (const float*)d_in[0];
    const int*   amask = (const int*)  d_in[1];
    const float* wq    = (const float*)d_in[2];
    const float* wk    = (const float*)d_in[3];
    const float* wv    = (const float*)d_in[4];
    const float* wo    = (const float*)d_in[5];
    const float* bo    = (const float*)d_in[6];
    const float* ln1s  = (const float*)d_in[7];
    const float* ln1b  = (const float*)d_in[8];
    const float* ln2s  = (const float*)d_in[9];
    const float* ln2b  = (const float*)d_in[10];
    const float* w1    = (const float*)d_in[11];
    const float* b1    = (const float*)d_in[12];
    const float* w2    = (const float*)d_in[13];
    const float* b2    = (const float*)d_in[14];
    float* out = (float*)d_out;

    __half *h, *qkvh, *ctx, *mid, *hwqkv, *hwo, *hw1, *hw2;
    float *x2;
    cudaGetSymbolAddress((void**)&h,     g_h);
    cudaGetSymbolAddress((void**)&qkvh,  g_qkvh);
    cudaGetSymbolAddress((void**)&ctx,   g_ctx);
    cudaGetSymbolAddress((void**)&x2,    g_x2);
    cudaGetSymbolAddress((void**)&mid,   g_mid);
    cudaGetSymbolAddress((void**)&hwqkv, g_hwqkv);
    cudaGetSymbolAddress((void**)&hwo,   g_hwo);
    cudaGetSymbolAddress((void**)&hw1,   g_hw1);
    cudaGetSymbolAddress((void**)&hw2,   g_hw2);

    cudaFuncSetAttribute(gemm_kernel<1>, cudaFuncAttributeMaxDynamicSharedMemorySize, GEMM_SMEM);
    cudaFuncSetAttribute(gemm_kernel<2>, cudaFuncAttributeMaxDynamicSharedMemorySize, GEMM_SMEM);
    cudaFuncSetAttribute(gemm_kernel<3>, cudaFuncAttributeMaxDynamicSharedMemorySize, GEMM_SMEM);
    cudaFuncSetAttribute(attn_kernel,    cudaFuncAttributeMaxDynamicSharedMemorySize, ATTN_SMEM);

    // merged weight prep (single launch)
    prep_weights<<<TOT_CH/256, 256>>>((const float4*)wq, (const float4*)wk,
                                      (const float4*)wv, (const float4*)wo,
                                      (const float4*)w1, (const float4*)w2,
                                      (uint2*)hwqkv, (uint2*)hwo,
                                      (uint2*)hw1,   (uint2*)hw2);

    // --- attention half ---
    ln_kernel<<<MTOT, 256>>>(x, ln1s, ln1b, h);
    gemm_kernel<3><<<dim3(3*DDIM/BN, MTOT/BM), 256, GEMM_SMEM>>>(
        h, hwqkv, nullptr, nullptr, qkvh, DDIM, 3*DDIM, 3*DDIM);
    attn_kernel<<<dim3(SS/QROWS, HH, BB), 256, ATTN_SMEM>>>(qkvh, amask, ctx);
    gemm_kernel<1><<<dim3(DDIM/BN, MTOT/BM), 256, GEMM_SMEM>>>(
        ctx, hwo, bo, x, x2, DDIM, DDIM, DDIM);

    // --- FFN half ---
    ln_kernel<<<MTOT, 256>>>(x2, ln2s, ln2b, h);
    gemm_kernel<2><<<dim3(DFF/BN, MTOT/BM), 256, GEMM_SMEM>>>(
        h, hw1, b1, nullptr, mid, DDIM, DFF, DFF);
    gemm_kernel<1><<<dim3(DDIM/BN, MTOT/BM), 256, GEMM_SMEM>>>(
        mid, hw2, b2, x2, out, DFF, DDIM, DDIM);
}

// round 16
// speedup vs baseline: 1.1184x; 1.0625x over previous
#include <cuda_runtime.h>
#include <cuda_fp16.h>
#include <cstdint>

// ---------------- problem dims ----------------
#define BB 4
#define SS 1024
#define DDIM 1024
#define HH 16
#define HDIM 64
#define DFF 4096
#define MTOT (BB*SS)   // 4096

// ---------------- device scratch (no allocs allowed) ----------------
__device__ __half g_h    [MTOT*DDIM];                 // LN output (half)
__device__ __half g_qkvh [(size_t)MTOT*3*DDIM];       // fused q|k|v (half)
__device__ __half g_ctx  [MTOT*DDIM];                 // attention output (half)
__device__ float  g_x2   [MTOT*DDIM];
__device__ __half g_mid  [(size_t)MTOT*DFF];          // FFN mid (half)
// half weights
__device__ __half g_hwqkv[(size_t)DDIM*3*DDIM];       // [K=1024][N=3072] concat
__device__ __half g_hwo  [DDIM*DDIM];
__device__ __half g_hw1  [(size_t)DDIM*DFF];
__device__ __half g_hw2  [(size_t)DFF*DDIM];

// ---------------- helpers ----------------
__device__ __forceinline__ void cp16(uint32_t dst, const void* src) {
    asm volatile("cp.async.cg.shared.global [%0], [%1], 16;" :: "r"(dst), "l"(src));
}
__device__ __forceinline__ void cpcommit() { asm volatile("cp.async.commit_group;"); }
template<int N> __device__ __forceinline__ void cpwait() {
    asm volatile("cp.async.wait_group %0;" :: "n"(N));
}
__device__ __forceinline__ float gelu_tanh(float v) {
    const float c = 0.79788456080286535588f;  // sqrt(2/pi)
    float u = c * (v + 0.044715f * v * v * v);
    return 0.5f * v * (1.f + tanhf(u));
}

#define MMA_F16(acc, a0,a1,a2,a3, b0,b1) \
    asm volatile( \
        "mma.sync.aligned.m16n8k16.row.col.f32.f16.f16.f32 " \
        "{%0,%1,%2,%3},{%4,%5,%6,%7},{%8,%9},{%0,%1,%2,%3};\n" \
        : "+f"((acc)[0]), "+f"((acc)[1]), "+f"((acc)[2]), "+f"((acc)[3]) \
        : "r"(a0), "r"(a1), "r"(a2), "r"(a3), "r"(b0), "r"(b1))

#define LDSM_X4(r0,r1,r2,r3, addr) \
    asm volatile("ldmatrix.sync.aligned.m8n8.x4.shared.b16 {%0,%1,%2,%3}, [%4];" \
        : "=r"(r0), "=r"(r1), "=r"(r2), "=r"(r3) : "r"(addr))
#define LDSM_X4T(r0,r1,r2,r3, addr) \
    asm volatile("ldmatrix.sync.aligned.m8n8.x4.trans.shared.b16 {%0,%1,%2,%3}, [%4];" \
        : "=r"(r0), "=r"(r1), "=r"(r2), "=r"(r3) : "r"(addr))

// ---------------- merged weight prep: fp32 -> fp16 (one launch) ----------------
#define QKV_CH  (DDIM * 3 * DDIM / 4)                 // 786432
#define WO_CH   (DDIM * DDIM / 4)                     // 262144
#define W1_CH   (DDIM * DFF / 4)                      // 1048576
#define W2_CH   (DFF * DDIM / 4)                      // 1048576
#define TOT_CH  (QKV_CH + WO_CH + W1_CH + W2_CH)      // 3145728

__global__ void prep_weights(const float4* __restrict__ wq, const float4* __restrict__ wk,
                             const float4* __restrict__ wv, const float4* __restrict__ wo,
                             const float4* __restrict__ w1, const float4* __restrict__ w2,
                             uint2* __restrict__ hwqkv, uint2* __restrict__ hwo,
                             uint2* __restrict__ hw1,   uint2* __restrict__ hw2) {
    int i = blockIdx.x * 256 + threadIdx.x;
    float4 v; uint2* dst; int di;
    if (i < QKV_CH) {
        int k = i / 768, nc = i % 768;
        const float4* src = (nc < 256) ? wq : (nc < 512) ? wk : wv;
        v = src[k * 256 + (nc & 255)];
        dst = hwqkv; di = i;
    } else if (i < QKV_CH + WO_CH) {
        di = i - QKV_CH; v = wo[di]; dst = hwo;
    } else if (i < QKV_CH + WO_CH + W1_CH) {
        di = i - QKV_CH - WO_CH; v = w1[di]; dst = hw1;
    } else {
        di = i - QKV_CH - WO_CH - W1_CH; v = w2[di]; dst = hw2;
    }
    __half2 h01 = __floats2half2_rn(v.x, v.y);
    __half2 h23 = __floats2half2_rn(v.z, v.w);
    uint2 o; o.x = *(uint32_t*)&h01; o.y = *(uint32_t*)&h23;
    dst[di] = o;
}

// ---------------- LayerNorm (row = 1024), output fp16 ----------------
__global__ void ln_kernel(const float* __restrict__ x,
                          const float* __restrict__ scale,
                          const float* __restrict__ shift,
                          __half* __restrict__ out) {
    int row = blockIdx.x;
    int t = threadIdx.x;
    const float4* xr = (const float4*)(x + (size_t)row * DDIM);
    float4 v = xr[t];
    float s  = v.x + v.y + v.z + v.w;
    float s2 = v.x*v.x + v.y*v.y + v.z*v.z + v.w*v.w;
    #pragma unroll
    for (int o = 16; o >= 1; o >>= 1) {
        s  += __shfl_xor_sync(0xffffffffu, s,  o);
        s2 += __shfl_xor_sync(0xffffffffu, s2, o);
    }
    __shared__ float red[2][8];
    __shared__ float bcast[2];
    int wid = t >> 5, lane = t & 31;
    if (lane == 0) { red[0][wid] = s; red[1][wid] = s2; }
    __syncthreads();
    if (t == 0) {
        float S = 0.f, S2 = 0.f;
        #pragma unroll
        for (int i = 0; i < 8; i++) { S += red[0][i]; S2 += red[1][i]; }
        float m = S * (1.f / DDIM);
        float var = S2 * (1.f / DDIM) - m * m;
        bcast[0] = m;
        bcast[1] = rsqrtf(var + 1e-5f);
    }
    __syncthreads();
    float m = bcast[0], inv = bcast[1];
    float4 sc = ((const float4*)scale)[t];
    float4 sh = ((const float4*)shift)[t];
    __half2 h01 = __floats2half2_rn(sc.x * (v.x - m) * inv + sh.x,
                                    sc.y * (v.y - m) * inv + sh.y);
    __half2 h23 = __floats2half2_rn(sc.z * (v.z - m) * inv + sh.z,
                                    sc.w * (v.w - m) * inv + sh.w);
    uint2 o2; o2.x = *(uint32_t*)&h01; o2.y = *(uint32_t*)&h23;
    ((uint2*)(out + (size_t)row * DDIM))[t] = o2;
}

// ---------------- FP16 mma GEMM: 4 warps, 64x64 warp tiles ----------------
// EPI: 0 fp32 store, 1 +bias+res fp32 store, 2 half gelu store, 3 plain half store
#define BM 128
#define BN 128
#define BKQ 32
#define ASTH 40
#define BSTH 136
#define NSTAGE 3

#define A_STG_H (BM * ASTH)    // 5120 halves
#define B_STG_H (BKQ * BSTH)   // 4352 halves
#define GEMM_SMEM ((NSTAGE * (A_STG_H + B_STG_H)) * 2)   // 56832 B

template<int EPI>
__global__ void __launch_bounds__(128, 2) gemm_kernel(
    const __half* __restrict__ A, const __half* __restrict__ Wt,
    const float* __restrict__ bias, const float* __restrict__ res,
    void* __restrict__ Cv, int Kdim, int Bld, int Cld)
{
    extern __shared__ __half smem[];
    __half* As = smem;
    __half* Bs = smem + NSTAGE * A_STG_H;

    const int tid  = threadIdx.x;
    const int bm0  = blockIdx.y * BM;
    const int bn0  = blockIdx.x * BN;
    const int wid  = tid >> 5, lane = tid & 31;
    const int wm   = wid >> 1;      // 0..1 (M, 64 rows)
    const int wn   = wid & 1;       // 0..1 (N, 64 cols)
    const int t4   = lane & 3;

    float acc[4][8][4];
    #pragma unroll
    for (int i = 0; i < 4; i++)
        #pragma unroll
        for (int j = 0; j < 8; j++)
            #pragma unroll
            for (int c = 0; c < 4; c++) acc[i][j][c] = 0.f;

    // ---- staging: 16B chunks, 128 threads x 8 chunks ----
    // A: 128 rows x 4 chunks; thread -> rows (t>>2)+{0,32,64,96}, col (t&3)*8
    // B: 32 rows x 16 chunks; thread -> rows (t>>4)+{0,8,16,24}, col (t&15)*8
    const int arow = tid >> 2, ac8 = tid & 3;
    const int brow = tid >> 4, bc16 = tid & 15;
    const __half* AgBase = A  + (size_t)(bm0 + arow) * Kdim + ac8 * 8;
    const __half* BgBase = Wt + (size_t)brow * Bld + bn0 + bc16 * 8;
    const uint32_t AsW = (uint32_t)__cvta_generic_to_shared(&As[arow * ASTH + ac8 * 8]);
    const uint32_t BsW = (uint32_t)__cvta_generic_to_shared(&Bs[brow * BSTH + bc16 * 8]);

    // ---- ldmatrix lane addresses ----
    const int lrow = lane & 15;
    const int lcol = (lane >> 4) * 8;
    uint32_t aLd[4];
    #pragma unroll
    for (int i = 0; i < 4; i++)
        aLd[i] = (uint32_t)__cvta_generic_to_shared(
            &As[(wm * 64 + i * 16 + lrow) * ASTH + lcol]);
    const int bkc = (lane >> 3) & 1, bjg = lane >> 4, br8 = lane & 7;
    const uint32_t bLd = (uint32_t)__cvta_generic_to_shared(
        &Bs[(bkc * 8 + br8) * BSTH + wn * 64 + bjg * 8]);

    const int KT = Kdim / BKQ;

    auto issue = [&](int kt) {
        const int st = kt % NSTAGE;
        const __half* Ag = AgBase + kt * BKQ;
        const __half* Bg = BgBase + (size_t)kt * BKQ * Bld;
        uint32_t ad = AsW + st * (A_STG_H * 2);
        uint32_t bd = BsW + st * (B_STG_H * 2);
        #pragma unroll
        for (int r = 0; r < 4; r++) {
            cp16(ad + r * 32 * ASTH * 2, Ag + (size_t)(r * 32) * Kdim);
            cp16(bd + r * 8  * BSTH * 2, Bg + (size_t)(r * 8)  * Bld);
        }
    };

    issue(0); cpcommit();
    issue(1); cpcommit();

    for (int kt = 0; kt < KT; kt++) {
        cpwait<1>();
        __syncthreads();

        if (kt + 2 < KT) issue(kt + 2);
        cpcommit();

        const int cb = kt % NSTAGE;
        const uint32_t aOff = cb * (A_STG_H * 2);
        const uint32_t bOff = cb * (B_STG_H * 2);

        #pragma unroll
        for (int s = 0; s < 2; s++) {          // two k16 steps per BKQ=32
            uint32_t bfr[8][2];
            #pragma unroll
            for (int p = 0; p < 4; p++) {      // n-octet pairs
                uint32_t r0, r1, r2, r3;
                LDSM_X4T(r0, r1, r2, r3, bLd + bOff + s * 16 * BSTH * 2 + p * 32);
                bfr[p*2  ][0] = r0; bfr[p*2  ][1] = r1;
                bfr[p*2+1][0] = r2; bfr[p*2+1][1] = r3;
            }
            #pragma unroll
            for (int i = 0; i < 4; i++) {
                uint32_t a0, a1, a2, a3;
                LDSM_X4(a0, a1, a2, a3, aLd[i] + aOff + s * 32);
                #pragma unroll
                for (int j = 0; j < 8; j++)
                    MMA_F16(acc[i][j], a0, a1, a2, a3, bfr[j][0], bfr[j][1]);
            }
        }
    }

    #pragma unroll
    for (int i = 0; i < 4; i++) {
        #pragma unroll
        for (int j = 0; j < 8; j++) {
            int r0 = bm0 + wm * 64 + i * 16 + (lane >> 2);
            int c0 = bn0 + wn * 64 + j * 8 + t4 * 2;
            #pragma unroll
            for (int half_ = 0; half_ < 2; half_++) {
                int r = r0 + half_ * 8;
                float vx = acc[i][j][half_ * 2], vy = acc[i][j][half_ * 2 + 1];
                if (EPI == 0) {
                    *(float2*)((float*)Cv + (size_t)r * Cld + c0) = make_float2(vx, vy);
                } else if (EPI == 1) {
                    float2 rr = *(const float2*)(res + (size_t)r * Cld + c0);
                    *(float2*)((float*)Cv + (size_t)r * Cld + c0) =
                        make_float2(vx + bias[c0] + rr.x, vy + bias[c0 + 1] + rr.y);
                } else if (EPI == 2) {
                    __half2 hv = __floats2half2_rn(gelu_tanh(vx + bias[c0]),
                                                   gelu_tanh(vy + bias[c0 + 1]));
                    *(__half2*)((__half*)Cv + (size_t)r * Cld + c0) = hv;
                } else {
                    *(__half2*)((__half*)Cv + (size_t)r * Cld + c0) =
                        __floats2half2_rn(vx, vy);
                }
            }
        }
    }
}

// ---------------- fp16 mma fused causal flash attention (proven R14) ----------------
#define QSTH 72
#define KSTH 72
#define VSTH 72
#define PSTH 72
#define QROWS 128
#define ATTN_SMEM ((QROWS*QSTH + 2*64*KSTH + 2*64*VSTH + 8*16*PSTH) * 2 + 2*64*4)  // 74240 B

__global__ void __launch_bounds__(256) attn_kernel(
    const __half* __restrict__ qkv, const int* __restrict__ mask,
    __half* __restrict__ ctx)
{
    extern __shared__ __half hsm[];
    __half* Qs = hsm;                             // QROWS*QSTH
    __half* Ks = Qs + QROWS * QSTH;               // 2 x 64*KSTH
    __half* Vs = Ks + 2 * 64 * KSTH;              // 2 x 64*VSTH
    __half* Pb = Vs + 2 * 64 * VSTH;              // 8 x 16*PSTH
    float*  Ms = (float*)(Pb + 8 * 16 * PSTH);    // 2 x 64

    const int b = blockIdx.z, h = blockIdx.y, qt = blockIdx.x;
    const int q0 = qt * QROWS;
    const int t = threadIdx.x;
    const int w = t >> 5, lane = t & 31;
    const int g = lane >> 2, t4 = lane & 3;
    __half* Pw = Pb + w * 16 * PSTH;

    {
        int row = t >> 1, ch = t & 1;
        const uint4* src = (const uint4*)(qkv + (size_t)(b * SS + q0 + row) * 3 * DDIM
                                          + h * HDIM) + ch * 4;
        __half2 scl = __floats2half2_rn(0.125f, 0.125f);
        uint4* dst = (uint4*)(Qs + row * QSTH + ch * 32);
        #pragma unroll
        for (int i = 0; i < 4; i++) {
            uint4 v = src[i];
            __half2* hp = (__half2*)&v;
            hp[0] = __hmul2(hp[0], scl); hp[1] = __hmul2(hp[1], scl);
            hp[2] = __hmul2(hp[2], scl); hp[3] = __hmul2(hp[3], scl);
            dst[i] = v;
        }
    }

    const int krow = t >> 2;
    const int kcol = (t & 3) * 16;
    const uint32_t KsW = (uint32_t)__cvta_generic_to_shared(&Ks[krow * KSTH + kcol]);
    const uint32_t VsW = (uint32_t)__cvta_generic_to_shared(&Vs[krow * VSTH + kcol]);

    auto issueKV = [&](int kt) {
        int st = kt & 1;
        const __half* base = qkv + (size_t)(b * SS + kt * 64 + krow) * 3 * DDIM
                             + h * HDIM + kcol;
        uint32_t ko = KsW + st * (64 * KSTH * 2);
        uint32_t vo = VsW + st * (64 * VSTH * 2);
        cp16(ko,      base + DDIM);
        cp16(ko + 16, base + DDIM + 8);
        cp16(vo,      base + 2 * DDIM);
        cp16(vo + 16, base + 2 * DDIM + 8);
    };

    const int lrow = lane & 15;
    const uint32_t qLd = (uint32_t)__cvta_generic_to_shared(
        &Qs[(w * 16 + lrow) * QSTH + (lane >> 4) * 8]);
    const uint32_t pLd = (uint32_t)__cvta_generic_to_shared(
        &Pw[lrow * PSTH + (lane >> 4) * 8]);
    const uint32_t kLd = (uint32_t)__cvta_generic_to_shared(
        &Ks[((lane & 7) + ((lane >> 4) & 1) * 8) * KSTH + ((lane >> 3) & 1) * 8]);
    const int bkc = (lane >> 3) & 1, bjg = lane >> 4, br8 = lane & 7;
    const uint32_t vLd = (uint32_t)__cvta_generic_to_shared(
        &Vs[(bkc * 8 + br8) * VSTH + bjg * 8]);

    float O[8][4];
    #pragma unroll
    for (int j = 0; j < 8; j++)
        #pragma unroll
        for (int c = 0; c < 4; c++) O[j][c] = 0.f;
    float m0 = -1e30f, m1 = -1e30f, l0 = 0.f, l1 = 0.f;
    const int qg0 = q0 + w * 16 + g, qg1 = qg0 + 8;
    const int myqmax = q0 + w * 16 + 15;
    const int ktmax = (q0 + QROWS - 1) >> 6;

    issueKV(0); cpcommit();
    if (t < 64) Ms[t] = mask[b * SS + t] ? 0.f : -1e30f;

    for (int kt = 0; kt <= ktmax; kt++) {
        cpwait<0>();
        __syncthreads();

        if (kt < ktmax) {
            issueKV(kt + 1);
            cpcommit();
            if (t < 64)
                Ms[((kt + 1) & 1) * 64 + t] =
                    mask[b * SS + (kt + 1) * 64 + t] ? 0.f : -1e30f;
        }

        if (kt * 64 <= myqmax) {
            const uint32_t kOff = (kt & 1) * (64 * KSTH * 2);
            const uint32_t vOff = (kt & 1) * (64 * VSTH * 2);
            const float* Msb = Ms + (kt & 1) * 64;

            float s[8][4];
            #pragma unroll
            for (int j = 0; j < 8; j++)
                #pragma unroll
                for (int c = 0; c < 4; c++) s[j][c] = 0.f;

            #pragma unroll
            for (int s4 = 0; s4 < 4; s4++) {
                uint32_t a0, a1, a2, a3;
                LDSM_X4(a0, a1, a2, a3, qLd + s4 * 32);
                #pragma unroll
                for (int j2 = 0; j2 < 4; j2++) {
                    uint32_t r0, r1, r2, r3;
                    LDSM_X4(r0, r1, r2, r3,
                            kLd + kOff + (j2 * 16 * KSTH + s4 * 16) * 2);
                    MMA_F16(s[j2*2],   a0, a1, a2, a3, r0, r1);
                    MMA_F16(s[j2*2+1], a0, a1, a2, a3, r2, r3);
                }
            }

            const bool diag = (kt * 64 + 63 > q0 + w * 16);
            float mt0 = -1e30f, mt1 = -1e30f;
            #pragma unroll
            for (int j = 0; j < 8; j++) {
                int n0 = j * 8 + 2 * t4;
                float pm0 = Msb[n0], pm1 = Msb[n0 + 1];
                float v0 = s[j][0] + pm0, v1 = s[j][1] + pm1;
                float v2 = s[j][2] + pm0, v3 = s[j][3] + pm1;
                if (diag) {
                    int kg = kt * 64 + n0;
                    if (kg     > qg0) v0 = -1e30f;
                    if (kg + 1 > qg0) v1 = -1e30f;
                    if (kg     > qg1) v2 = -1e30f;
                    if (kg + 1 > qg1) v3 = -1e30f;
                }
                s[j][0] = v0; s[j][1] = v1; s[j][2] = v2; s[j][3] = v3;
                mt0 = fmaxf(mt0, fmaxf(v0, v1));
                mt1 = fmaxf(mt1, fmaxf(v2, v3));
            }
            mt0 = fmaxf(mt0, __shfl_xor_sync(0xffffffffu, mt0, 1));
            mt0 = fmaxf(mt0, __shfl_xor_sync(0xffffffffu, mt0, 2));
            mt1 = fmaxf(mt1, __shfl_xor_sync(0xffffffffu, mt1, 1));
            mt1 = fmaxf(mt1, __shfl_xor_sync(0xffffffffu, mt1, 2));

            float mn0 = fmaxf(m0, mt0), mn1 = fmaxf(m1, mt1);
            float corr0 = __expf(m0 - mn0), corr1 = __expf(m1 - mn1);
            m0 = mn0; m1 = mn1;

            float ls0 = 0.f, ls1 = 0.f;
            #pragma unroll
            for (int j = 0; j < 8; j++) {
                float p0 = __expf(s[j][0] - mn0);
                float p1 = __expf(s[j][1] - mn0);
                float p2 = __expf(s[j][2] - mn1);
                float p3 = __expf(s[j][3] - mn1);
                ls0 += p0 + p1; ls1 += p2 + p3;
                int n0 = j * 8 + 2 * t4;
                *(__half2*)&Pw[g * PSTH + n0]       = __floats2half2_rn(p0, p1);
                *(__half2*)&Pw[(g + 8) * PSTH + n0] = __floats2half2_rn(p2, p3);
            }
            ls0 += __shfl_xor_sync(0xffffffffu, ls0, 1);
            ls0 += __shfl_xor_sync(0xffffffffu, ls0, 2);
            ls1 += __shfl_xor_sync(0xffffffffu, ls1, 1);
            ls1 += __shfl_xor_sync(0xffffffffu, ls1, 2);
            l0 = l0 * corr0 + ls0;
            l1 = l1 * corr1 + ls1;

            #pragma unroll
            for (int j = 0; j < 8; j++) {
                O[j][0] *= corr0; O[j][1] *= corr0;
                O[j][2] *= corr1; O[j][3] *= corr1;
            }
            __syncwarp();

            #pragma unroll
            for (int s4 = 0; s4 < 4; s4++) {
                uint32_t a0, a1, a2, a3;
                LDSM_X4(a0, a1, a2, a3, pLd + s4 * 32);
                #pragma unroll
                for (int p = 0; p < 4; p++) {
                    uint32_t r0, r1, r2, r3;
                    LDSM_X4T(r0, r1, r2, r3,
                             vLd + vOff + (s4 * 16 * VSTH + p * 16) * 2);
                    MMA_F16(O[p*2],   a0, a1, a2, a3, r0, r1);
                    MMA_F16(O[p*2+1], a0, a1, a2, a3, r2, r3);
                }
            }
            __syncwarp();
        }
    }

    float inv0 = 1.f / l0, inv1 = 1.f / l1;
    __half* o0 = ctx + (size_t)(b * SS + qg0) * DDIM + h * HDIM;
    __half* o1 = ctx + (size_t)(b * SS + qg1) * DDIM + h * HDIM;
    #pragma unroll
    for (int j = 0; j < 8; j++) {
        int n0 = j * 8 + 2 * t4;
        *(__half2*)(o0 + n0) = __floats2half2_rn(O[j][0] * inv0, O[j][1] * inv0);
        *(__half2*)(o1 + n0) = __floats2half2_rn(O[j][2] * inv1, O[j][3] * inv1);
    }
}

// ---------------- launch ----------------
extern "C" void kernel_launch(void* const* d_in, const int* in_sizes, int n_in,
                              void* d_out, int out_size) {
    const float* x     = (const float*)d_in[0];
    const int*   amask = (const int*)  d_in[1];
    const float* wq    = (const float*)d_in[2];
    const float* wk    = (const float*)d_in[3];
    const float* wv    = (const float*)d_in[4];
    const float* wo    = (const float*)d_in[5];
    const float* bo    = (const float*)d_in[6];
    const float* ln1s  = (const float*)d_in[7];
    const float* ln1b  = (const float*)d_in[8];
    const float* ln2s  = (const float*)d_in[9];
    const float* ln2b  = (const float*)d_in[10];
    const float* w1    = (const float*)d_in[11];
    const float* b1    = (const float*)d_in[12];
    const float* w2    = (const float*)d_in[13];
    const float* b2    = (const float*)d_in[14];
    float* out = (float*)d_out;

    __half *h, *qkvh, *ctx, *mid, *hwqkv, *hwo, *hw1, *hw2;
    float *x2;
    cudaGetSymbolAddress((void**)&h,     g_h);
    cudaGetSymbolAddress((void**)&qkvh,  g_qkvh);
    cudaGetSymbolAddress((void**)&ctx,   g_ctx);
    cudaGetSymbolAddress((void**)&x2,    g_x2);
    cudaGetSymbolAddress((void**)&mid,   g_mid);
    cudaGetSymbolAddress((void**)&hwqkv, g_hwqkv);
    cudaGetSymbolAddress((void**)&hwo,   g_hwo);
    cudaGetSymbolAddress((void**)&hw1,   g_hw1);
    cudaGetSymbolAddress((void**)&hw2,   g_hw2);

    cudaFuncSetAttribute(gemm_kernel<1>, cudaFuncAttributeMaxDynamicSharedMemorySize, GEMM_SMEM);
    cudaFuncSetAttribute(gemm_kernel<2>, cudaFuncAttributeMaxDynamicSharedMemorySize, GEMM_SMEM);
    cudaFuncSetAttribute(gemm_kernel<3>, cudaFuncAttributeMaxDynamicSharedMemorySize, GEMM_SMEM);
    cudaFuncSetAttribute(attn_kernel,    cudaFuncAttributeMaxDynamicSharedMemorySize, ATTN_SMEM);

    // merged weight prep (single launch)
    prep_weights<<<TOT_CH/256, 256>>>((const float4*)wq, (const float4*)wk,
                                      (const float4*)wv, (const float4*)wo,
                                      (const float4*)w1, (const float4*)w2,
                                      (uint2*)hwqkv, (uint2*)hwo,
                                      (uint2*)hw1,   (uint2*)hw2);

    // --- attention half ---
    ln_kernel<<<MTOT, 256>>>(x, ln1s, ln1b, h);
    gemm_kernel<3><<<dim3(3*DDIM/BN, MTOT/BM), 128, GEMM_SMEM>>>(
        h, hwqkv, nullptr, nullptr, qkvh, DDIM, 3*DDIM, 3*DDIM);
    attn_kernel<<<dim3(SS/QROWS, HH, BB), 256, ATTN_SMEM>>>(qkvh, amask, ctx);
    gemm_kernel<1><<<dim3(DDIM/BN, MTOT/BM), 128, GEMM_SMEM>>>(
        ctx, hwo, bo, x, x2, DDIM, DDIM, DDIM);

    // --- FFN half ---
    ln_kernel<<<MTOT, 256>>>(x2, ln2s, ln2b, h);
    gemm_kernel<2><<<dim3(DFF/BN, MTOT/BM), 128, GEMM_SMEM>>>(
        h, hw1, b1, nullptr, mid, DDIM, DFF, DFF);
    gemm_kernel<1><<<dim3(DDIM/BN, MTOT/BM), 128, GEMM_SMEM>>>(
        mid, hw2, b2, x2, out, DFF, DDIM, DDIM);
}